// round 13
// baseline (speedup 1.0000x reference)
#include <cuda_runtime.h>
#include <math.h>

// MultiConvPerm — memset + edge-only kernel.
// 94.4% of the output is zero: let the driver's memset path write it
// (graph memset node, near-peak DRAM write BW), then a small kernel computes
// the 57-tap acc per row and writes only the two edge windows:
//   out[x] = acc[28-x]    for x in [0,28]
//   out[x] = acc[W+28-x]  for x in [W-28, W-1]
// acc[t] = sum over static (wi,j) with t = p_wi + d_wi*j of coef[wi]*w_wi[row,j]
// coef   = softmax(alpha + gumbels)   (log_softmax shift cancels)

#define NW 12
#define NROWS 65536            // CO*CI = 256*256
#define WARPS_PER_BLOCK 8
#define ROWS_PER_WARP 4

struct WPtrs {
    const float* w[NW];
};

// compile-time tap geometry (KD = product((3,5,7,9),(1,3,7)), S=57)
__device__ __forceinline__ void tap_params(int wi, int& k, int& d, int& p) {
    const int ks[NW] = {3,3,3, 5,5,5, 7,7,7, 9,9,9};
    const int ds[NW] = {1,3,7, 1,3,7, 1,3,7, 1,3,7};
    const int ps[NW] = {27,25,21, 26,22,14, 25,19,7, 24,16,0};
    k = ks[wi]; d = ds[wi]; p = ps[wi];
}

template<bool FAST1024>
__global__ __launch_bounds__(WARPS_PER_BLOCK * 32)
void multiconv_edges(WPtrs wp, const float* __restrict__ alpha,
                     const float* __restrict__ gumbels,
                     float* __restrict__ out, int W) {
    __shared__ float s_acc[WARPS_PER_BLOCK][ROWS_PER_WARP][64];

    const int tid = threadIdx.x;
    const int warp = tid >> 5;
    const int lane = tid & 31;

    const int row0 = (blockIdx.x * WARPS_PER_BLOCK + warp) * ROWS_PER_WARP;

    // ---- coef = softmax(alpha + gumbels), fast-math, per-thread ------------
    float coef[NW];
    {
        float m = -1e30f;
        #pragma unroll
        for (int i = 0; i < NW; i++) {
            coef[i] = alpha[i] + gumbels[i];
            m = fmaxf(m, coef[i]);
        }
        float s = 0.0f;
        #pragma unroll
        for (int i = 0; i < NW; i++) {
            coef[i] = __expf(coef[i] - m);
            s += coef[i];
        }
        const float inv = __fdividef(1.0f, s);
        #pragma unroll
        for (int i = 0; i < NW; i++) coef[i] *= inv;
    }

    // ---- per-lane accumulators over static taps ----------------------------
    // lane owns t0 = lane and t1 = lane+32 (valid while t1 <= 56)
    float f0[ROWS_PER_WARP], f1[ROWS_PER_WARP];
    #pragma unroll
    for (int r = 0; r < ROWS_PER_WARP; r++) { f0[r] = 0.0f; f1[r] = 0.0f; }

    const bool hasHi = (lane < 25);

    #pragma unroll
    for (int wi = 0; wi < NW; wi++) {
        int k, d, p;
        tap_params(wi, k, d, p);

        const int u0 = lane - p;
        const int u1 = lane + 32 - p;
        const bool v0 = (u0 >= 0) && (u0 % d == 0) && (u0 / d < k);
        const bool v1 = hasHi && (u1 >= 0) && (u1 % d == 0) && (u1 / d < k);
        const int j0 = u0 / d;
        const int j1 = u1 / d;

        const float c = coef[wi];
        const float* base = wp.w[wi] + (size_t)row0 * k;
        #pragma unroll
        for (int r = 0; r < ROWS_PER_WARP; r++) {
            if (v0) f0[r] += c * base[r * k + j0];
            if (v1) f1[r] += c * base[r * k + j1];
        }
    }

    #pragma unroll
    for (int r = 0; r < ROWS_PER_WARP; r++) {
        s_acc[warp][r][lane] = f0[r];
        if (hasHi) s_acc[warp][r][lane + 32] = f1[r];
    }
    __syncwarp();

    // ---- edge stores only (memset already wrote the zeros) -----------------
    if (FAST1024) {
        // one STG.128 per row, 16 active lanes:
        //   lanes 0..7  -> head floats [0,32)    (zeros beyond 28 are harmless)
        //   lanes 8..15 -> tail floats [992,1024) (zeros before 996 harmless)
        #pragma unroll
        for (int r = 0; r < ROWS_PER_WARP; r++) {
            const float* A = s_acc[warp][r];
            float* orow = out + (size_t)(row0 + r) * 1024;
            if (lane < 16) {
                const int x = (lane < 8) ? (lane * 4) : (992 + (lane - 8) * 4);
                float4 v;
                #pragma unroll
                for (int q = 0; q < 4; q++) {
                    const int xx = x + q;
                    float f = 0.0f;
                    if (xx < 32) {
                        if (xx < 29) f = A[28 - xx];
                    } else {
                        if (xx >= 996) f = A[1052 - xx];
                    }
                    (&v.x)[q] = f;
                }
                *reinterpret_cast<float4*>(orow + x) = v;
            }
        }
    } else {
        // generic W: write head floats [0,29) and tail [W-28, W) scalar-safe
        #pragma unroll
        for (int r = 0; r < ROWS_PER_WARP; r++) {
            const float* A = s_acc[warp][r];
            float* orow = out + (size_t)(row0 + r) * (size_t)W;
            if (lane < 29) orow[lane] = A[28 - lane];                    // x=lane
            if (lane < 28) orow[W - 28 + lane] = A[56 - lane];           // x=W-28+lane -> acc[W+28-x]=acc[56-lane]
        }
    }
}

extern "C" void kernel_launch(void* const* d_in, const int* in_sizes, int n_in,
                              void* d_out, int out_size) {
    WPtrs wp;
    for (int i = 0; i < NW; i++) wp.w[i] = (const float*)d_in[i];
    const float* alpha = (const float*)d_in[12];
    const float* gumbels = (const float*)d_in[13];
    float* out = (float*)d_out;

    const int W = out_size / NROWS;  // spatial size (1024)

    // 1) zero the whole output via the driver memset path (graph memset node)
    cudaMemsetAsync(d_out, 0, (size_t)out_size * sizeof(float), 0);

    // 2) write only the nonzero edge windows
    const int rows_per_block = WARPS_PER_BLOCK * ROWS_PER_WARP;
    const int grid = (NROWS + rows_per_block - 1) / rows_per_block;

    if (W == 1024) {
        multiconv_edges<true><<<grid, WARPS_PER_BLOCK * 32>>>(wp, alpha, gumbels, out, W);
    } else {
        multiconv_edges<false><<<grid, WARPS_PER_BLOCK * 32>>>(wp, alpha, gumbels, out, W);
    }
}

// round 15
// speedup vs baseline: 1.0298x; 1.0298x over previous
#include <cuda_runtime.h>
#include <math.h>

// MultiConvPerm — memset + row-per-thread edge kernel.
// 94.4% of the output is zero: a graph memset node writes it at near-peak
// DRAM BW (~7.3 TB/s measured), then each THREAD computes one row's 57-tap
// acc entirely in registers with compile-time tap indices (no predication,
// no smem, no syncs) and writes only the two edge windows:
//   out[x] = acc[28-x]     for x in [0,28]
//   out[x] = acc[1052-x]   for x in [996,1023]   (W=1024)
// acc[t] = sum over static (wi,j) with t = p_wi + d_wi*j of coef[wi]*w_wi[row,j]
// coef   = softmax(alpha + gumbels)   (log_softmax shift cancels)

#define NW 12
#define NROWS 65536            // CO*CI = 256*256
#define S_LEN 57

struct WPtrs {
    const float* w[NW];
};

// ---------------- fast path: one thread = one row (W == 1024) ---------------
__global__ __launch_bounds__(128)
void multiconv_rows(WPtrs wp, const float* __restrict__ alpha,
                    const float* __restrict__ gumbels,
                    float* __restrict__ out) {
    const int row = blockIdx.x * blockDim.x + threadIdx.x;
    if (row >= NROWS) return;

    // ---- coef = softmax(alpha + gumbels), fast-math ------------------------
    float coef[NW];
    {
        float m = -1e30f;
        #pragma unroll
        for (int i = 0; i < NW; i++) {
            coef[i] = alpha[i] + gumbels[i];
            m = fmaxf(m, coef[i]);
        }
        float s = 0.0f;
        #pragma unroll
        for (int i = 0; i < NW; i++) {
            coef[i] = __expf(coef[i] - m);
            s += coef[i];
        }
        const float inv = __fdividef(1.0f, s);
        #pragma unroll
        for (int i = 0; i < NW; i++) coef[i] *= inv;
    }

    // ---- dense tap accumulation, all indices compile-time ------------------
    float acc[S_LEN];
    #pragma unroll
    for (int t = 0; t < S_LEN; t++) acc[t] = 0.0f;

    #pragma unroll
    for (int wi = 0; wi < NW; wi++) {
        const int ks[NW] = {3,3,3, 5,5,5, 7,7,7, 9,9,9};
        const int ds[NW] = {1,3,7, 1,3,7, 1,3,7, 1,3,7};
        const int ps[NW] = {27,25,21, 26,22,14, 25,19,7, 24,16,0};
        const int k = ks[wi], d = ds[wi], p = ps[wi];
        const float c = coef[wi];
        const float* base = wp.w[wi] + (size_t)row * k;
        #pragma unroll
        for (int j = 0; j < 9; j++) {
            if (j < k) acc[p + d * j] += c * base[j];   // folds to literals
        }
    }

    // ---- edge stores straight from registers -------------------------------
    float* orow = out + (size_t)row * 1024;

    // head: floats [0,32): out[x] = acc[28-x] for x<=28, else 0 (memset'd ok)
    #pragma unroll
    for (int g = 0; g < 8; g++) {
        float4 v;
        #pragma unroll
        for (int q = 0; q < 4; q++) {
            const int t = 28 - (4 * g + q);
            (&v.x)[q] = (t >= 0) ? acc[t] : 0.0f;
        }
        *reinterpret_cast<float4*>(orow + 4 * g) = v;
    }
    // tail: floats [996,1024): out[x] = acc[1052-x], t = 56-4g-q in [29,56]
    #pragma unroll
    for (int g = 0; g < 7; g++) {
        float4 v;
        #pragma unroll
        for (int q = 0; q < 4; q++) {
            const int t = 56 - (4 * g + q);
            (&v.x)[q] = acc[t];
        }
        *reinterpret_cast<float4*>(orow + 996 + 4 * g) = v;
    }
}

// ---------------- generic-W fallback (full-row writer, proven path) ---------
__global__ __launch_bounds__(256)
void multiconv_generic(WPtrs wp, const float* __restrict__ alpha,
                       const float* __restrict__ gumbels,
                       float* __restrict__ out, int W) {
    __shared__ float s_acc[8][4][64];
    __shared__ float s_coef[NW];

    const int tid = threadIdx.x;
    const int warp = tid >> 5;
    const int lane = tid & 31;
    const int row0 = (blockIdx.x * 8 + warp) * 4;

    if (tid < NW) {
        float v[NW];
        float m = -1e30f;
        #pragma unroll
        for (int i = 0; i < NW; i++) {
            v[i] = alpha[i] + gumbels[i];
            m = fmaxf(m, v[i]);
        }
        float s = 0.0f;
        #pragma unroll
        for (int i = 0; i < NW; i++) { v[i] = __expf(v[i] - m); s += v[i]; }
        s_coef[tid] = v[tid] * __fdividef(1.0f, s);
    }
    __syncthreads();

    float f0[4], f1[4];
    #pragma unroll
    for (int r = 0; r < 4; r++) { f0[r] = 0.0f; f1[r] = 0.0f; }

    const bool hasHi = (lane < 25);
    #pragma unroll
    for (int wi = 0; wi < NW; wi++) {
        const int ks[NW] = {3,3,3, 5,5,5, 7,7,7, 9,9,9};
        const int ds[NW] = {1,3,7, 1,3,7, 1,3,7, 1,3,7};
        const int ps[NW] = {27,25,21, 26,22,14, 25,19,7, 24,16,0};
        const int k = ks[wi], d = ds[wi], p = ps[wi];
        const int u0 = lane - p, u1 = lane + 32 - p;
        const bool v0 = (u0 >= 0) && (u0 % d == 0) && (u0 / d < k);
        const bool v1 = hasHi && (u1 >= 0) && (u1 % d == 0) && (u1 / d < k);
        const int j0 = u0 / d, j1 = u1 / d;
        const float c = s_coef[wi];
        const float* base = wp.w[wi] + (size_t)row0 * k;
        #pragma unroll
        for (int r = 0; r < 4; r++) {
            if (v0) f0[r] += c * base[r * k + j0];
            if (v1) f1[r] += c * base[r * k + j1];
        }
    }
    #pragma unroll
    for (int r = 0; r < 4; r++) {
        s_acc[warp][r][lane] = f0[r];
        if (hasHi) s_acc[warp][r][lane + 32] = f1[r];
    }
    __syncwarp();

    const int lo = 29, hi = W - 28;
    #pragma unroll
    for (int r = 0; r < 4; r++) {
        const float* A = s_acc[warp][r];
        float* orow = out + (size_t)(row0 + r) * (size_t)W;
        for (int x0 = lane * 4; x0 < W; x0 += 128) {
            float4 v;
            #pragma unroll
            for (int q = 0; q < 4; q++) {
                const int x = x0 + q;
                float f = 0.0f;
                if (x < lo) f = A[28 - x];
                else if (x >= hi) f = A[W + 28 - x];
                (&v.x)[q] = f;
            }
            *reinterpret_cast<float4*>(orow + x0) = v;
        }
    }
}

extern "C" void kernel_launch(void* const* d_in, const int* in_sizes, int n_in,
                              void* d_out, int out_size) {
    WPtrs wp;
    for (int i = 0; i < NW; i++) wp.w[i] = (const float*)d_in[i];
    const float* alpha = (const float*)d_in[12];
    const float* gumbels = (const float*)d_in[13];
    float* out = (float*)d_out;

    const int W = out_size / NROWS;  // spatial size (1024)

    if (W == 1024) {
        // 1) zero everything via the driver memset path (graph memset node)
        cudaMemsetAsync(d_out, 0, (size_t)out_size * sizeof(float), 0);
        // 2) row-per-thread edge writer
        multiconv_rows<<<NROWS / 128, 128>>>(wp, alpha, gumbels, out);
    } else {
        const int grid = (NROWS + 31) / 32;
        multiconv_generic<<<grid, 256>>>(wp, alpha, gumbels, out, W);
    }
}

// round 16
// speedup vs baseline: 1.2162x; 1.1810x over previous
#include <cuda_runtime.h>
#include <math.h>

// MultiConvPerm — memset + row-per-thread edge kernel with coalesced stores.
// A graph memset node zeros the whole 256MB output (~7.3 TB/s), then each
// THREAD computes one row's 57-tap acc in registers (compile-time tap indices)
// and stages the permuted 64 edge floats to smem; warps then store row-major
// (2 rows per STG.128 round -> 4 L1 wavefronts/instr instead of 32).
//   out[x] = acc[28-x]     for x in [0,28]
//   out[x] = acc[1052-x]   for x in [996,1023]   (W=1024)
// acc[t] = sum over static (wi,j) with t = p_wi + d_wi*j of coef[wi]*w_wi[row,j]
// coef   = softmax(alpha + gumbels)   (log_softmax shift cancels)

#define NW 12
#define NROWS 65536            // CO*CI = 256*256
#define S_LEN 57
#define TPB 128                // threads (=rows) per block
#define SROW 68                // smem row stride in floats (pad vs bank conflicts)

struct WPtrs {
    const float* w[NW];
};

// ---------------- fast path: one thread = one row (W == 1024) ---------------
__global__ __launch_bounds__(TPB)
void multiconv_rows(WPtrs wp, const float* __restrict__ alpha,
                    const float* __restrict__ gumbels,
                    float* __restrict__ out) {
    __shared__ float s_edge[TPB][SROW];   // [0,32): head out vals, [32,64): tail

    const int tid = threadIdx.x;
    const int warp = tid >> 5;
    const int lane = tid & 31;
    const int row = blockIdx.x * TPB + tid;

    // ---- coef = softmax(alpha + gumbels), fast-math ------------------------
    float coef[NW];
    {
        float m = -1e30f;
        #pragma unroll
        for (int i = 0; i < NW; i++) {
            coef[i] = alpha[i] + gumbels[i];
            m = fmaxf(m, coef[i]);
        }
        float s = 0.0f;
        #pragma unroll
        for (int i = 0; i < NW; i++) {
            coef[i] = __expf(coef[i] - m);
            s += coef[i];
        }
        const float inv = __fdividef(1.0f, s);
        #pragma unroll
        for (int i = 0; i < NW; i++) coef[i] *= inv;
    }

    // ---- dense tap accumulation, all indices compile-time ------------------
    float acc[S_LEN];
    #pragma unroll
    for (int t = 0; t < S_LEN; t++) acc[t] = 0.0f;

    #pragma unroll
    for (int wi = 0; wi < NW; wi++) {
        const int ks[NW] = {3,3,3, 5,5,5, 7,7,7, 9,9,9};
        const int ds[NW] = {1,3,7, 1,3,7, 1,3,7, 1,3,7};
        const int ps[NW] = {27,25,21, 26,22,14, 25,19,7, 24,16,0};
        const int k = ks[wi], d = ds[wi], p = ps[wi];
        const float c = coef[wi];
        const float* base = wp.w[wi] + (size_t)row * k;
        #pragma unroll
        for (int j = 0; j < 9; j++) {
            if (j < k) acc[p + d * j] += c * base[j];   // folds to literals
        }
    }

    // ---- stage permuted edge floats to smem --------------------------------
    // head: s[tid][x]    = out[x]     = (x<=28)   ? acc[28-x]        : 0
    // tail: s[tid][32+i] = out[992+i] = (i>=4)    ? acc[60-i]        : 0
    #pragma unroll
    for (int x = 0; x < 32; x++) {
        s_edge[tid][x] = (x <= 28) ? acc[28 - x] : 0.0f;
    }
    #pragma unroll
    for (int i = 0; i < 32; i++) {
        s_edge[tid][32 + i] = (i >= 4) ? acc[60 - i] : 0.0f;
    }
    __syncwarp();

    // ---- coalesced row-major stores: 2 rows per round ----------------------
    // lane l: local row lr = 2*iter + (l>>4); segment g = l&15
    //   g in [0,8): head float4 g       -> gmem offset 4*g
    //   g in [8,16): tail float4 (g-8)  -> gmem offset 992 + 4*(g-8)
    const int rbase = blockIdx.x * TPB + warp * 32;   // first row this warp owns
    const int g = lane & 15;
    const int half = lane >> 4;
    const int goff = (g < 8) ? (4 * g) : (992 + 4 * (g - 8));

    #pragma unroll
    for (int iter = 0; iter < 16; iter++) {
        const int lr = 2 * iter + half;               // 0..31
        const float* src = &s_edge[warp * 32 + lr][4 * g];
        float4 v = make_float4(src[0], src[1], src[2], src[3]);
        float* dst = out + (size_t)(rbase + lr) * 1024 + goff;
        *reinterpret_cast<float4*>(dst) = v;
    }
}

// ---------------- generic-W fallback (full-row writer, proven path) ---------
__global__ __launch_bounds__(256)
void multiconv_generic(WPtrs wp, const float* __restrict__ alpha,
                       const float* __restrict__ gumbels,
                       float* __restrict__ out, int W) {
    __shared__ float s_acc[8][4][64];
    __shared__ float s_coef[NW];

    const int tid = threadIdx.x;
    const int warp = tid >> 5;
    const int lane = tid & 31;
    const int row0 = (blockIdx.x * 8 + warp) * 4;

    if (tid < NW) {
        float v[NW];
        float m = -1e30f;
        #pragma unroll
        for (int i = 0; i < NW; i++) {
            v[i] = alpha[i] + gumbels[i];
            m = fmaxf(m, v[i]);
        }
        float s = 0.0f;
        #pragma unroll
        for (int i = 0; i < NW; i++) { v[i] = __expf(v[i] - m); s += v[i]; }
        s_coef[tid] = v[tid] * __fdividef(1.0f, s);
    }
    __syncthreads();

    float f0[4], f1[4];
    #pragma unroll
    for (int r = 0; r < 4; r++) { f0[r] = 0.0f; f1[r] = 0.0f; }

    const bool hasHi = (lane < 25);
    #pragma unroll
    for (int wi = 0; wi < NW; wi++) {
        const int ks[NW] = {3,3,3, 5,5,5, 7,7,7, 9,9,9};
        const int ds[NW] = {1,3,7, 1,3,7, 1,3,7, 1,3,7};
        const int ps[NW] = {27,25,21, 26,22,14, 25,19,7, 24,16,0};
        const int k = ks[wi], d = ds[wi], p = ps[wi];
        const int u0 = lane - p, u1 = lane + 32 - p;
        const bool v0 = (u0 >= 0) && (u0 % d == 0) && (u0 / d < k);
        const bool v1 = hasHi && (u1 >= 0) && (u1 % d == 0) && (u1 / d < k);
        const int j0 = u0 / d, j1 = u1 / d;
        const float c = s_coef[wi];
        const float* base = wp.w[wi] + (size_t)row0 * k;
        #pragma unroll
        for (int r = 0; r < 4; r++) {
            if (v0) f0[r] += c * base[r * k + j0];
            if (v1) f1[r] += c * base[r * k + j1];
        }
    }
    #pragma unroll
    for (int r = 0; r < 4; r++) {
        s_acc[warp][r][lane] = f0[r];
        if (hasHi) s_acc[warp][r][lane + 32] = f1[r];
    }
    __syncwarp();

    const int lo = 29, hi = W - 28;
    #pragma unroll
    for (int r = 0; r < 4; r++) {
        const float* A = s_acc[warp][r];
        float* orow = out + (size_t)(row0 + r) * (size_t)W;
        for (int x0 = lane * 4; x0 < W; x0 += 128) {
            float4 v;
            #pragma unroll
            for (int q = 0; q < 4; q++) {
                const int x = x0 + q;
                float f = 0.0f;
                if (x < lo) f = A[28 - x];
                else if (x >= hi) f = A[W + 28 - x];
                (&v.x)[q] = f;
            }
            *reinterpret_cast<float4*>(orow + x0) = v;
        }
    }
}

extern "C" void kernel_launch(void* const* d_in, const int* in_sizes, int n_in,
                              void* d_out, int out_size) {
    WPtrs wp;
    for (int i = 0; i < NW; i++) wp.w[i] = (const float*)d_in[i];
    const float* alpha = (const float*)d_in[12];
    const float* gumbels = (const float*)d_in[13];
    float* out = (float*)d_out;

    const int W = out_size / NROWS;  // spatial size (1024)

    if (W == 1024) {
        // 1) zero everything via the driver memset path (graph memset node)
        cudaMemsetAsync(d_out, 0, (size_t)out_size * sizeof(float), 0);
        // 2) row-per-thread edge writer with coalesced stores
        multiconv_rows<<<NROWS / TPB, TPB>>>(wp, alpha, gumbels, out);
    } else {
        const int grid = (NROWS + 31) / 32;
        multiconv_generic<<<grid, 256>>>(wp, alpha, gumbels, out, W);
    }
}